// round 16
// baseline (speedup 1.0000x reference)
#include <cuda_runtime.h>
#include <cstdint>

#define BB 1024
#define TT 128
#define FIN 17
#define HID 64
#define NH 4
#define HD 16
#define MROWS (BB*TT)

#define OFF_CROP   0
#define OFF_PHENO  3072
#define OFF_INNOV  920576
#define OFF_UNC    1838080
#define OFF_XFIN   1839104
#define OFF_STATE  1846272

typedef unsigned long long u64;

__device__ __forceinline__ u64 pk(float a, float b) {
    u64 r;
    asm("mov.b64 %0, {%1, %2};" : "=l"(r) : "r"(__float_as_uint(a)), "r"(__float_as_uint(b)));
    return r;
}
__device__ __forceinline__ void unpk(u64 v, float& a, float& b) {
    unsigned x, y;
    asm("mov.b64 {%0, %1}, %2;" : "=r"(x), "=r"(y) : "l"(v));
    a = __uint_as_float(x); b = __uint_as_float(y);
}
__device__ __forceinline__ u64 f2fma(u64 a, u64 b, u64 c) {
    u64 d;
    asm("fma.rn.f32x2 %0, %1, %2, %3;" : "=l"(d) : "l"(a), "l"(b), "l"(c));
    return d;
}
__device__ __forceinline__ u64 f2mul(u64 a, u64 b) {
    u64 d;
    asm("mul.rn.f32x2 %0, %1, %2;" : "=l"(d) : "l"(a), "l"(b));
    return d;
}

__device__ float g_h[MROWS*HID];
__device__ float g_q[MROWS*HID];
__device__ float g_k[MROWS*HID];
__device__ float g_v[MROWS*HID];
__device__ float g_ctx[MROWS*HID];
__device__ float g_ao[MROWS*HID];
__device__ float g_pool[2048*64];
__device__ float g_K[TT*49];
__device__ float g_P[49];
__device__ float g_trace;
__device__ float g_chaos[BB];
__device__ float g_gate[BB*NH];

// ---------------- K0: Riccati stage (t0..t1), P carried in g_P ----------------
__global__ void k0_riccati(const float* __restrict__ A, int t0, int t1,
                           int initP, int finalP)
{
    __shared__ float As[49], P[49], Mm[49], Pp[49], W[49], X[49];
    int tid = threadIdx.x;
    int r = tid / 7, c = tid % 7;
    if (tid < 49) {
        As[tid] = A[tid];
        P[tid] = initP ? ((r == c) ? 0.1f : 0.f) : g_P[tid];
    }
    __syncthreads();
    for (int t = t0; t < t1; t++) {
        if (tid < 49) {
            float s = 0.f;
            #pragma unroll
            for (int jx = 0; jx < 7; jx++) s += As[r*7+jx] * P[jx*7+c];
            Mm[tid] = s;
        }
        __syncthreads();
        if (tid < 49) {
            float s = (r == c) ? 0.5f : 0.f;
            #pragma unroll
            for (int jx = 0; jx < 7; jx++) s += Mm[r*7+jx] * As[c*7+jx];
            Pp[tid] = s;
            W[tid]  = s + ((r == c) ? 0.5f : 0.f);
            X[tid]  = s;
        }
        __syncthreads();
        for (int k = 0; k < 7; k++) {
            float f = 0.f;
            if (tid < 49) f = W[r*7+k] * (1.f / W[k*7+k]);
            __syncthreads();
            if (tid < 49 && r != k) {
                W[tid] -= f * W[k*7+c];
                X[tid] -= f * X[k*7+c];
            }
            __syncthreads();
        }
        if (tid < 49) X[tid] = X[tid] / W[r*7+r];
        __syncthreads();
        if (tid < 49) {
            g_K[t*49 + tid] = X[c*7 + r];
            float s = Pp[tid];
            #pragma unroll
            for (int jx = 0; jx < 7; jx++) s -= X[jx*7+r] * Pp[jx*7+c];
            Mm[tid] = s;
        }
        __syncthreads();
        if (tid < 49) P[tid] = Mm[tid];
        __syncthreads();
    }
    if (tid < 49) g_P[tid] = P[tid];
    if (finalP && tid == 0) {
        float tr = 0.f;
        #pragma unroll
        for (int i = 0; i < 7; i++) tr += P[i*7+i];
        g_trace = tr;
    }
}

// ---------------- K1: scan, per-sub named barriers + 4-acc meas ----------------
__global__ __launch_bounds__(256) void k1_scan(
    const float* __restrict__ x,
    const float* __restrict__ W_in, const float* __restrict__ b_in,
    const float* __restrict__ W_exec, const float* __restrict__ b_exec,
    const float* __restrict__ W_meas, const float* __restrict__ b_meas,
    const float* __restrict__ A,
    float* __restrict__ dout)
{
    __shared__ __align__(16) float s_z[2][136];
    __shared__ float s_part[2][2][64];
    __shared__ float s_wm[448];
    __shared__ float s_wi[17*64];
    __shared__ float s_A[49];
    __shared__ float s_K[2][2][49];
    __shared__ float s_x[2][8];
    __shared__ float s_innov[2][8];

    int tid = threadIdx.x;
    int sub = tid >> 7;
    int half = (tid >> 6) & 1;
    int j = tid & 63;
    int lt = tid & 127;
    int b = blockIdx.x*2 + sub;
    int barAB = 2 + sub;
    int barC  = 4 + sub;

    u64 w2[34];
    #pragma unroll
    for (int k2 = 0; k2 < 34; k2++) {
        int g0 = half*68 + 2*k2, g1 = g0 + 1;
        float f0 = (g0 < 135) ? W_exec[g0*64 + j] : 0.f;
        float f1 = (g1 < 135) ? W_exec[g1*64 + j] : 0.f;
        w2[k2] = pk(f0, f1);
    }
    for (int i=tid;i<17*64;i+=256) s_wi[i]=W_in[i];
    for (int i=tid;i<448;i+=256)   s_wm[i]=W_meas[i];
    if (tid<49) s_A[tid]=A[tid];
    for (int i=tid;i<272;i+=256) s_z[i/136][i%136]=0.f;
    if (tid<16) s_x[tid>>3][tid&7]=0.f;
    float bex = b_exec[j];
    float bin = b_in[j];
    float bme = (j<7)? b_meas[j] : 0.f;
    __syncthreads();

    float acc2 = 0.f;
    float xv[FIN];
    if (half==0) {
        const float* xr = x + ((size_t)b*TT)*FIN;
        #pragma unroll
        for (int f=0;f<FIN;f++) xv[f]=__ldg(xr+f);
    }

    for (int t=0;t<TT;t++) {
        size_t row = (size_t)b*TT + t;
        if (half==0) {
            float hv = bin;
            #pragma unroll
            for (int f=0;f<FIN;f++) hv = fmaf(xv[f], s_wi[f*64+j], hv);
            g_h[row*64+j] = hv;
            s_z[sub][j] = hv;
            if (j<7) {
                float xp=0.f;
                #pragma unroll
                for (int kx=0;kx<7;kx++) xp = fmaf(s_A[j*7+kx], s_x[sub][kx], xp);
                s_z[sub][64+j] = xp;
            }
            if (lt<49) s_K[sub][t&1][lt] = g_K[t*49+lt];
            if (t+1 < TT) {
                const float* xr = x + (row+1)*FIN;
                #pragma unroll
                for (int f=0;f<FIN;f++) xv[f]=__ldg(xr+f);
            }
        }
        asm volatile("bar.sync %0, 128;" :: "r"(barAB) : "memory");
        u64 pA = 0ULL, pB = 0ULL;
        const ulonglong2* zp = (const ulonglong2*)&s_z[sub][half*68];
        #pragma unroll
        for (int k2 = 0; k2 < 17; k2++) {
            ulonglong2 zv = zp[k2];
            pA = f2fma(zv.x, w2[2*k2],   pA);
            pB = f2fma(zv.y, w2[2*k2+1], pB);
        }
        float u0,u1,u2,u3;
        unpk(pA, u0, u1); unpk(pB, u2, u3);
        s_part[sub][half][j] = (u0+u1)+(u2+u3);
        asm volatile("bar.sync %0, 128;" :: "r"(barAB) : "memory");
        if (half==0) {
            float a = s_part[sub][0][j] + s_part[sub][1][j] + bex;
            float hn = tanhf(a);
            s_z[sub][71+j] = hn;
            asm volatile("bar.sync %0, 64;" :: "r"(barC) : "memory");
            if (j<7) {
                float m0 = bme, m1 = 0.f, m2 = 0.f, m3 = 0.f;
                #pragma unroll
                for (int k=0;k<64;k+=4) {
                    m0 = fmaf(s_z[sub][71+k+0], s_wm[(k+0)*7+j], m0);
                    m1 = fmaf(s_z[sub][71+k+1], s_wm[(k+1)*7+j], m1);
                    m2 = fmaf(s_z[sub][71+k+2], s_wm[(k+2)*7+j], m2);
                    m3 = fmaf(s_z[sub][71+k+3], s_wm[(k+3)*7+j], m3);
                }
                float inn = ((m0+m1)+(m2+m3)) - s_z[sub][64+j];
                s_innov[sub][j] = inn;
                dout[OFF_INNOV + row*7 + j] = inn;
                acc2 = fmaf(inn, inn, acc2);
            }
            __syncwarp();
            if (j<7) {
                float xn = s_z[sub][64+j];
                #pragma unroll
                for (int kx=0;kx<7;kx++) xn = fmaf(s_K[sub][t&1][j*7+kx], s_innov[sub][kx], xn);
                s_x[sub][j] = xn;
                dout[OFF_STATE + row*7 + j] = xn;
            }
            __syncwarp();
        }
    }
    if (half==0) {
        acc2 += __shfl_down_sync(0xffffffffu, acc2, 4);
        acc2 += __shfl_down_sync(0xffffffffu, acc2, 2);
        acc2 += __shfl_down_sync(0xffffffffu, acc2, 1);
        if (j==0) g_chaos[b] = acc2;
        if (j<7) dout[OFF_XFIN + b*7 + j] = s_x[sub][j];
    }
}

// ---------------- K2: gate + uncertainty ----------------
__global__ void k2_gate(const float* __restrict__ hurst,
                        const float* __restrict__ Wp, const float* __restrict__ bp,
                        float* __restrict__ dout)
{
    int idx = blockIdx.x*256 + threadIdx.x;
    if (idx >= BB*NH) return;
    int b = idx >> 2, h = idx & 3;
    float c = fminf(g_chaos[b] * (1.f/896.f), 10.f) * 0.1f;
    float z = c*Wp[h] + hurst[b]*Wp[4+h] + bp[h];
    g_gate[idx] = 1.f / (1.f + __expf(-z));
    if (h==0) dout[OFF_UNC + b] = g_trace;
}

// ---- 2-cols-per-thread matvec over 16 rows/thread, packed (proven) ----
__device__ __forceinline__ void gemm2col(
    const float* __restrict__ Wg, const float* __restrict__ bg,
    float* __restrict__ outg, const float* s_a, int cp, int rg, int r0)
{
    u64 w0[32], w1[32];
    #pragma unroll
    for (int k2 = 0; k2 < 32; k2++) {
        float2 ra = *(const float2*)&Wg[(2*k2)*64 + cp];
        float2 rb = *(const float2*)&Wg[(2*k2+1)*64 + cp];
        w0[k2] = pk(ra.x, rb.x);
        w1[k2] = pk(ra.y, rb.y);
    }
    float b0 = bg[cp], b1 = bg[cp+1];
    for (int rr = 0; rr < 16; rr++) {
        int lr = rg*16 + rr;
        const ulonglong2* ap = (const ulonglong2*)(s_a + lr*64);
        u64 x01 = 0ULL, x23 = 0ULL, y01 = 0ULL, y23 = 0ULL;
        #pragma unroll
        for (int k4 = 0; k4 < 16; k4++) {
            ulonglong2 av = ap[k4];
            x01 = f2fma(av.x, w0[2*k4],   x01);
            x23 = f2fma(av.y, w0[2*k4+1], x23);
            y01 = f2fma(av.x, w1[2*k4],   y01);
            y23 = f2fma(av.y, w1[2*k4+1], y23);
        }
        float xa,xb,xc,xd, ya,yb,yc,yd;
        unpk(x01,xa,xb); unpk(x23,xc,xd);
        unpk(y01,ya,yb); unpk(y23,yc,yd);
        *(float2*)&outg[(size_t)(r0+lr)*64 + cp] =
            make_float2(b0 + (xa+xb)+(xc+xd), b1 + (ya+yb)+(yc+yd));
    }
}

// ---------------- K3: fused a_in + QKV, 64 rows/block (proven, 192us) ----------------
__global__ __launch_bounds__(128) void k3_ain_qkv(
    const float* __restrict__ Wa, const float* __restrict__ ba,
    const float* __restrict__ Wq, const float* __restrict__ bq,
    const float* __restrict__ Wk, const float* __restrict__ bk,
    const float* __restrict__ Wv, const float* __restrict__ bv,
    const float* __restrict__ dout)
{
    __shared__ __align__(16) float s_in[64*72];
    __shared__ __align__(16) float s_a[64*64];
    int tid = threadIdx.x;
    int r0 = blockIdx.x * 64;
    for (int i = tid; i < 64*72; i += 128) {
        int lr = i / 72, c = i - lr*72;
        float v;
        if (c < 64)      v = g_h[(size_t)(r0+lr)*64 + c];
        else if (c < 71) v = dout[OFF_STATE + (size_t)(r0+lr)*7 + (c-64)];
        else             v = 0.f;
        s_in[i] = v;
    }
    __syncthreads();
    int cp = (tid & 31) * 2;
    int rg = tid >> 5;
    {
        u64 w0[36], w1[36];
        #pragma unroll
        for (int k2 = 0; k2 < 36; k2++) {
            int ka = 2*k2, kb = 2*k2+1;
            float2 ra = (ka < 71) ? *(const float2*)&Wa[ka*64 + cp] : make_float2(0.f,0.f);
            float2 rb = (kb < 71) ? *(const float2*)&Wa[kb*64 + cp] : make_float2(0.f,0.f);
            w0[k2] = pk(ra.x, rb.x);
            w1[k2] = pk(ra.y, rb.y);
        }
        float b0 = ba[cp], b1 = ba[cp+1];
        for (int rr = 0; rr < 16; rr++) {
            int lr = rg*16 + rr;
            const ulonglong2* ip = (const ulonglong2*)(s_in + lr*72);
            u64 x01=0ULL, x23=0ULL, y01=0ULL, y23=0ULL;
            #pragma unroll
            for (int k4 = 0; k4 < 18; k4++) {
                ulonglong2 iv = ip[k4];
                x01 = f2fma(iv.x, w0[2*k4],   x01);
                x23 = f2fma(iv.y, w0[2*k4+1], x23);
                y01 = f2fma(iv.x, w1[2*k4],   y01);
                y23 = f2fma(iv.y, w1[2*k4+1], y23);
            }
            float xa,xb,xc,xd, ya,yb,yc,yd;
            unpk(x01,xa,xb); unpk(x23,xc,xd);
            unpk(y01,ya,yb); unpk(y23,yc,yd);
            s_a[lr*64 + cp]   = b0 + (xa+xb)+(xc+xd);
            s_a[lr*64 + cp+1] = b1 + (ya+yb)+(yc+yd);
        }
    }
    __syncthreads();
    gemm2col(Wq, bq, g_q, s_a, cp, rg, r0);
    gemm2col(Wk, bk, g_k, s_a, cp, rg, r0);
    gemm2col(Wv, bv, g_v, s_a, cp, rg, r0);
}

// ---------------- K4: attention, chunked online softmax, gate folded into Q ----------------
__global__ __launch_bounds__(64) void k4_attn()
{
    __shared__ __align__(16) float k_s[128*16];
    __shared__ __align__(16) float v_s[128*16];
    int bh = blockIdx.x;
    int b = bh >> 2, h = bh & 3;
    int tid = threadIdx.x;
    size_t base = ((size_t)b*TT)*64 + h*HD;

    for (int r = tid; r < 128; r += 64) {
        const float4* kg = (const float4*)&g_k[base + (size_t)r*64];
        float4* ks = (float4*)&k_s[r*16];
        ks[0]=kg[0]; ks[1]=kg[1]; ks[2]=kg[2]; ks[3]=kg[3];
        const float4* vg = (const float4*)&g_v[base + (size_t)r*64];
        float4* vs = (float4*)&v_s[r*16];
        vs[0]=vg[0]; vs[1]=vg[1]; vs[2]=vg[2]; vs[3]=vg[3];
    }
    int qA = tid*2, qB = tid*2 + 1;
    const ulonglong2* qap = (const ulonglong2*)&g_q[base + (size_t)qA*64];
    const ulonglong2* qbp = (const ulonglong2*)&g_q[base + (size_t)qB*64];
    ulonglong2 qa01 = qap[0], qa23 = qap[1], qa45 = qap[2], qa67 = qap[3];
    ulonglong2 qb01 = qbp[0], qb23 = qbp[1], qb45 = qbp[2], qb67 = qbp[3];
    float sc = g_gate[b*NH + h] * 0.25f;
    u64 sc2 = pk(sc, sc);
    qa01.x = f2mul(qa01.x, sc2); qa01.y = f2mul(qa01.y, sc2);
    qa23.x = f2mul(qa23.x, sc2); qa23.y = f2mul(qa23.y, sc2);
    qa45.x = f2mul(qa45.x, sc2); qa45.y = f2mul(qa45.y, sc2);
    qa67.x = f2mul(qa67.x, sc2); qa67.y = f2mul(qa67.y, sc2);
    qb01.x = f2mul(qb01.x, sc2); qb01.y = f2mul(qb01.y, sc2);
    qb23.x = f2mul(qb23.x, sc2); qb23.y = f2mul(qb23.y, sc2);
    qb45.x = f2mul(qb45.x, sc2); qb45.y = f2mul(qb45.y, sc2);
    qb67.x = f2mul(qb67.x, sc2); qb67.y = f2mul(qb67.y, sc2);
    __syncthreads();

    float mA = -1e30f, lA = 0.f, mB = -1e30f, lB = 0.f;
    u64 accA[8], accB[8];
    #pragma unroll
    for (int d = 0; d < 8; d++) { accA[d]=0ULL; accB[d]=0ULL; }
    float sA8[8], sB8[8];

    for (int c = 0; c < 16; c++) {
        int kk0 = c*8;
        float cmA = -1e30f, cmB = -1e30f;
        #pragma unroll
        for (int i = 0; i < 8; i++) {
            const ulonglong2* kr = (const ulonglong2*)&k_s[(kk0+i)*16];
            ulonglong2 k01 = kr[0], k23 = kr[1], k45 = kr[2], k67 = kr[3];
            u64 dA = f2mul(qa01.x, k01.x);
            dA = f2fma(qa01.y, k01.y, dA);
            dA = f2fma(qa23.x, k23.x, dA);
            dA = f2fma(qa23.y, k23.y, dA);
            dA = f2fma(qa45.x, k45.x, dA);
            dA = f2fma(qa45.y, k45.y, dA);
            dA = f2fma(qa67.x, k67.x, dA);
            dA = f2fma(qa67.y, k67.y, dA);
            u64 dB = f2mul(qb01.x, k01.x);
            dB = f2fma(qb01.y, k01.y, dB);
            dB = f2fma(qb23.x, k23.x, dB);
            dB = f2fma(qb23.y, k23.y, dB);
            dB = f2fma(qb45.x, k45.x, dB);
            dB = f2fma(qb45.y, k45.y, dB);
            dB = f2fma(qb67.x, k67.x, dB);
            dB = f2fma(qb67.y, k67.y, dB);
            float a0,a1,b0,b1;
            unpk(dA, a0, a1); unpk(dB, b0, b1);
            float sA = a0+a1, sB = b0+b1;
            sA8[i] = sA; sB8[i] = sB;
            cmA = fmaxf(cmA, sA); cmB = fmaxf(cmB, sB);
        }
        float mnA = fmaxf(mA, cmA), mnB = fmaxf(mB, cmB);
        float rA = __expf(mA - mnA), rB = __expf(mB - mnB);
        mA = mnA; mB = mnB;
        lA *= rA; lB *= rB;
        u64 rA2 = pk(rA, rA), rB2 = pk(rB, rB);
        #pragma unroll
        for (int d = 0; d < 8; d++) {
            accA[d] = f2mul(accA[d], rA2);
            accB[d] = f2mul(accB[d], rB2);
        }
        #pragma unroll
        for (int i = 0; i < 8; i++) {
            float pA = __expf(sA8[i] - mA);
            float pB = __expf(sB8[i] - mB);
            lA += pA; lB += pB;
            u64 pA2 = pk(pA, pA), pB2 = pk(pB, pB);
            const ulonglong2* vr = (const ulonglong2*)&v_s[(kk0+i)*16];
            ulonglong2 v01 = vr[0], v23 = vr[1], v45 = vr[2], v67 = vr[3];
            accA[0] = f2fma(pA2, v01.x, accA[0]);
            accA[1] = f2fma(pA2, v01.y, accA[1]);
            accA[2] = f2fma(pA2, v23.x, accA[2]);
            accA[3] = f2fma(pA2, v23.y, accA[3]);
            accA[4] = f2fma(pA2, v45.x, accA[4]);
            accA[5] = f2fma(pA2, v45.y, accA[5]);
            accA[6] = f2fma(pA2, v67.x, accA[6]);
            accA[7] = f2fma(pA2, v67.y, accA[7]);
            accB[0] = f2fma(pB2, v01.x, accB[0]);
            accB[1] = f2fma(pB2, v01.y, accB[1]);
            accB[2] = f2fma(pB2, v23.x, accB[2]);
            accB[3] = f2fma(pB2, v23.y, accB[3]);
            accB[4] = f2fma(pB2, v45.x, accB[4]);
            accB[5] = f2fma(pB2, v45.y, accB[5]);
            accB[6] = f2fma(pB2, v67.x, accB[6]);
            accB[7] = f2fma(pB2, v67.y, accB[7]);
        }
    }
    float invA = 1.f / lA, invB = 1.f / lB;
    float oA[16], oB[16];
    #pragma unroll
    for (int d = 0; d < 8; d++) {
        unpk(accA[d], oA[2*d], oA[2*d+1]);
        unpk(accB[d], oB[2*d], oB[2*d+1]);
    }
    float4* oa = (float4*)&g_ctx[base + (size_t)qA*64];
    float4* ob = (float4*)&g_ctx[base + (size_t)qB*64];
    #pragma unroll
    for (int d = 0; d < 4; d++) {
        oa[d] = make_float4(oA[4*d]*invA, oA[4*d+1]*invA, oA[4*d+2]*invA, oA[4*d+3]*invA);
        ob[d] = make_float4(oB[4*d]*invB, oB[4*d+1]*invB, oB[4*d+2]*invB, oB[4*d+3]*invB);
    }
}

// ---------------- K5: attn_out + fused pheno + fused partial pooling ----------------
__global__ __launch_bounds__(128) void k5_wo(
    const float* __restrict__ Wo, const float* __restrict__ bo,
    const float* __restrict__ Wp, const float* __restrict__ bp,
    float* __restrict__ dout)
{
    __shared__ __align__(16) float s_c[64*64];
    __shared__ __align__(16) float s_o[64*72];
    __shared__ float s_wp[448];
    __shared__ float s_ps[4][64];
    int tid = threadIdx.x;
    int r0 = blockIdx.x * 64;
    for (int i = tid; i < 4096; i += 128) s_c[i] = g_ctx[(size_t)r0*64 + i];
    for (int i = tid; i < 448; i += 128) s_wp[i] = Wp[i];
    __syncthreads();
    int cp = (tid & 31) * 2;
    int rg = tid >> 5;
    {
        u64 w0[32], w1[32];
        #pragma unroll
        for (int k2 = 0; k2 < 32; k2++) {
            float2 ra = *(const float2*)&Wo[(2*k2)*64 + cp];
            float2 rb = *(const float2*)&Wo[(2*k2+1)*64 + cp];
            w0[k2] = pk(ra.x, rb.x);
            w1[k2] = pk(ra.y, rb.y);
        }
        float b0 = bo[cp], b1 = bo[cp+1];
        float ps0 = 0.f, ps1 = 0.f;
        for (int rr = 0; rr < 16; rr++) {
            int lr = rg*16 + rr;
            const ulonglong2* ap = (const ulonglong2*)(s_c + lr*64);
            u64 x01 = 0ULL, x23 = 0ULL, y01 = 0ULL, y23 = 0ULL;
            #pragma unroll
            for (int k4 = 0; k4 < 16; k4++) {
                ulonglong2 av = ap[k4];
                x01 = f2fma(av.x, w0[2*k4],   x01);
                x23 = f2fma(av.y, w0[2*k4+1], x23);
                y01 = f2fma(av.x, w1[2*k4],   y01);
                y23 = f2fma(av.y, w1[2*k4+1], y23);
            }
            float xa,xb,xc,xd, ya,yb,yc,yd;
            unpk(x01,xa,xb); unpk(x23,xc,xd);
            unpk(y01,ya,yb); unpk(y23,yc,yd);
            float o0 = b0 + (xa+xb)+(xc+xd);
            float o1 = b1 + (ya+yb)+(yc+yd);
            ps0 += o0; ps1 += o1;
            *(float2*)&g_ao[(size_t)(r0+lr)*64 + cp] = make_float2(o0, o1);
            *(float2*)&s_o[lr*72 + cp] = make_float2(o0, o1);
        }
        s_ps[rg][cp] = ps0;
        s_ps[rg][cp+1] = ps1;
    }
    __syncthreads();
    if (tid < 64) {
        g_pool[(size_t)blockIdx.x*64 + tid] =
            s_ps[0][tid] + s_ps[1][tid] + s_ps[2][tid] + s_ps[3][tid];
    }
    for (int o = tid; o < 448; o += 128) {
        int lr = o / 7, n = o - lr*7;
        float a0 = bp[n], a1 = 0.f, a2 = 0.f, a3 = 0.f;
        const float4* tp = (const float4*)(s_o + lr*72);
        #pragma unroll
        for (int k4 = 0; k4 < 16; k4++) {
            float4 tv = tp[k4];
            a0 = fmaf(tv.x, s_wp[(4*k4+0)*7 + n], a0);
            a1 = fmaf(tv.y, s_wp[(4*k4+1)*7 + n], a1);
            a2 = fmaf(tv.z, s_wp[(4*k4+2)*7 + n], a2);
            a3 = fmaf(tv.w, s_wp[(4*k4+3)*7 + n], a3);
        }
        dout[OFF_PHENO + (size_t)(r0+lr)*7 + n] = (a0+a1)+(a2+a3);
    }
}

// ---------------- K6: LN + crop from pooled partials ----------------
__global__ __launch_bounds__(64) void k6_pool(
    const float* __restrict__ lng, const float* __restrict__ lnb,
    const float* __restrict__ Wc, const float* __restrict__ bc,
    float* __restrict__ dout)
{
    __shared__ float s_y[64];
    __shared__ float red[2];
    int b = blockIdx.x, tid = threadIdx.x;
    float pool = (g_pool[(size_t)(2*b)*64 + tid] + g_pool[(size_t)(2*b+1)*64 + tid]) * (1.f/128.f);
    float v = pool;
    #pragma unroll
    for (int off = 16; off >= 1; off >>= 1) v += __shfl_down_sync(0xffffffffu, v, off);
    if ((tid & 31) == 0) red[tid >> 5] = v;
    __syncthreads();
    float mean = (red[0] + red[1]) * (1.f/64.f);
    __syncthreads();
    float d = pool - mean;
    v = d * d;
    #pragma unroll
    for (int off = 16; off >= 1; off >>= 1) v += __shfl_down_sync(0xffffffffu, v, off);
    if ((tid & 31) == 0) red[tid >> 5] = v;
    __syncthreads();
    float var = (red[0] + red[1]) * (1.f/64.f);
    float y = d * rsqrtf(var + 1e-5f) * lng[tid] + lnb[tid];
    s_y[tid] = y;
    __syncthreads();
    if (tid < 3) {
        float acc = bc[tid];
        #pragma unroll 8
        for (int jx = 0; jx < 64; jx++) acc += s_y[jx] * Wc[jx*3 + tid];
        dout[OFF_CROP + b*3 + tid] = acc;
    }
}

extern "C" void kernel_launch(void* const* d_in, const int* in_sizes, int n_in,
                              void* d_out, int out_size)
{
    const float* x      = (const float*)d_in[0];
    const float* hurst  = (const float*)d_in[2];
    const float* W_in   = (const float*)d_in[3];
    const float* b_in   = (const float*)d_in[4];
    const float* W_exec = (const float*)d_in[5];
    const float* b_exec = (const float*)d_in[6];
    const float* W_meas = (const float*)d_in[7];
    const float* b_meas = (const float*)d_in[8];
    const float* A      = (const float*)d_in[9];
    const float* W_attn = (const float*)d_in[10];
    const float* b_attn = (const float*)d_in[11];
    const float* Wq     = (const float*)d_in[12];
    const float* bq     = (const float*)d_in[13];
    const float* Wk     = (const float*)d_in[14];
    const float* bk     = (const float*)d_in[15];
    const float* Wv     = (const float*)d_in[16];
    const float* bv     = (const float*)d_in[17];
    const float* Wo     = (const float*)d_in[18];
    const float* bo     = (const float*)d_in[19];
    const float* W_phys = (const float*)d_in[20];
    const float* b_phys = (const float*)d_in[21];
    const float* ln_g   = (const float*)d_in[22];
    const float* ln_b   = (const float*)d_in[23];
    const float* W_crop = (const float*)d_in[24];
    const float* b_crop = (const float*)d_in[25];
    const float* W_phen = (const float*)d_in[26];
    const float* b_phen = (const float*)d_in[27];
    float* out = (float*)d_out;

    k0_riccati<<<1, 64>>>(A, 0,  43, 1, 0);
    k0_riccati<<<1, 64>>>(A, 43, 86, 0, 0);
    k0_riccati<<<1, 64>>>(A, 86, 128, 0, 1);
    k1_scan<<<BB/2, 256>>>(x, W_in, b_in, W_exec, b_exec, W_meas, b_meas, A, out);
    k2_gate<<<(BB*NH + 255)/256, 256>>>(hurst, W_phys, b_phys, out);
    k3_ain_qkv<<<MROWS/64, 128>>>(W_attn, b_attn, Wq, bq, Wk, bk, Wv, bv, out);
    k4_attn<<<BB*NH, 64>>>();
    k5_wo<<<MROWS/64, 128>>>(Wo, bo, W_phen, b_phen, out);
    k6_pool<<<BB, 64>>>(ln_g, ln_b, W_crop, b_crop, out);
}

// round 17
// speedup vs baseline: 1.1256x; 1.1256x over previous
#include <cuda_runtime.h>
#include <cstdint>

#define BB 1024
#define TT 128
#define FIN 17
#define HID 64
#define NH 4
#define HD 16
#define MROWS (BB*TT)

#define OFF_CROP   0
#define OFF_PHENO  3072
#define OFF_INNOV  920576
#define OFF_UNC    1838080
#define OFF_XFIN   1839104
#define OFF_STATE  1846272

typedef unsigned long long u64;

__device__ __forceinline__ u64 pk(float a, float b) {
    u64 r;
    asm("mov.b64 %0, {%1, %2};" : "=l"(r) : "r"(__float_as_uint(a)), "r"(__float_as_uint(b)));
    return r;
}
__device__ __forceinline__ void unpk(u64 v, float& a, float& b) {
    unsigned x, y;
    asm("mov.b64 {%0, %1}, %2;" : "=r"(x), "=r"(y) : "l"(v));
    a = __uint_as_float(x); b = __uint_as_float(y);
}
__device__ __forceinline__ u64 f2fma(u64 a, u64 b, u64 c) {
    u64 d;
    asm("fma.rn.f32x2 %0, %1, %2, %3;" : "=l"(d) : "l"(a), "l"(b), "l"(c));
    return d;
}
__device__ __forceinline__ u64 f2mul(u64 a, u64 b) {
    u64 d;
    asm("mul.rn.f32x2 %0, %1, %2;" : "=l"(d) : "l"(a), "l"(b));
    return d;
}

__device__ float g_h[MROWS*HID];
__device__ float g_q[MROWS*HID];
__device__ float g_k[MROWS*HID];
__device__ float g_v[MROWS*HID];
__device__ float g_ctx[MROWS*HID];
__device__ float g_ao[MROWS*HID];
__device__ float g_pool[2048*64];
__device__ float g_K[TT*49];
__device__ float g_P[49];
__device__ float g_trace;
__device__ float g_chaos[BB];
__device__ float g_gate[BB*NH];

// ---------------- K0: Riccati stage ----------------
__global__ void k0_riccati(const float* __restrict__ A, int t0, int t1,
                           int initP, int finalP)
{
    __shared__ float As[49], P[49], Mm[49], Pp[49], W[49], X[49];
    int tid = threadIdx.x;
    int r = tid / 7, c = tid % 7;
    if (tid < 49) {
        As[tid] = A[tid];
        P[tid] = initP ? ((r == c) ? 0.1f : 0.f) : g_P[tid];
    }
    __syncthreads();
    for (int t = t0; t < t1; t++) {
        if (tid < 49) {
            float s = 0.f;
            #pragma unroll
            for (int jx = 0; jx < 7; jx++) s += As[r*7+jx] * P[jx*7+c];
            Mm[tid] = s;
        }
        __syncthreads();
        if (tid < 49) {
            float s = (r == c) ? 0.5f : 0.f;
            #pragma unroll
            for (int jx = 0; jx < 7; jx++) s += Mm[r*7+jx] * As[c*7+jx];
            Pp[tid] = s;
            W[tid]  = s + ((r == c) ? 0.5f : 0.f);
            X[tid]  = s;
        }
        __syncthreads();
        for (int k = 0; k < 7; k++) {
            float f = 0.f;
            if (tid < 49) f = W[r*7+k] * (1.f / W[k*7+k]);
            __syncthreads();
            if (tid < 49 && r != k) {
                W[tid] -= f * W[k*7+c];
                X[tid] -= f * X[k*7+c];
            }
            __syncthreads();
        }
        if (tid < 49) X[tid] = X[tid] / W[r*7+r];
        __syncthreads();
        if (tid < 49) {
            g_K[t*49 + tid] = X[c*7 + r];
            float s = Pp[tid];
            #pragma unroll
            for (int jx = 0; jx < 7; jx++) s -= X[jx*7+r] * Pp[jx*7+c];
            Mm[tid] = s;
        }
        __syncthreads();
        if (tid < 49) P[tid] = Mm[tid];
        __syncthreads();
    }
    if (tid < 49) g_P[tid] = P[tid];
    if (finalP && tid == 0) {
        float tr = 0.f;
        #pragma unroll
        for (int i = 0; i < 7; i++) tr += P[i*7+i];
        g_trace = tr;
    }
}

// ---------------- K1: scan, ONE batch row per 128-thread block ----------------
__global__ __launch_bounds__(128) void k1_scan(
    const float* __restrict__ x,
    const float* __restrict__ W_in, const float* __restrict__ b_in,
    const float* __restrict__ W_exec, const float* __restrict__ b_exec,
    const float* __restrict__ W_meas, const float* __restrict__ b_meas,
    const float* __restrict__ A,
    float* __restrict__ dout)
{
    __shared__ __align__(16) float s_z[136];
    __shared__ float s_part[2][64];
    __shared__ float s_wm[448];
    __shared__ float s_wi[17*64];
    __shared__ float s_A[49];
    __shared__ float s_K[2][49];
    __shared__ float s_x[8];
    __shared__ float s_innov[8];

    int tid = threadIdx.x;
    int half = tid >> 6;
    int j = tid & 63;
    int b = blockIdx.x;

    u64 w2[34];
    #pragma unroll
    for (int k2 = 0; k2 < 34; k2++) {
        int g0 = half*68 + 2*k2, g1 = g0 + 1;
        float f0 = (g0 < 135) ? W_exec[g0*64 + j] : 0.f;
        float f1 = (g1 < 135) ? W_exec[g1*64 + j] : 0.f;
        w2[k2] = pk(f0, f1);
    }
    for (int i=tid;i<17*64;i+=128) s_wi[i]=W_in[i];
    for (int i=tid;i<448;i+=128)   s_wm[i]=W_meas[i];
    if (tid<49) s_A[tid]=A[tid];
    for (int i=tid;i<136;i+=128) s_z[i]=0.f;
    if (tid<8) s_x[tid]=0.f;
    float bex = b_exec[j];
    float bin = b_in[j];
    float bme = (j<7)? b_meas[j] : 0.f;
    __syncthreads();

    float acc2 = 0.f;
    float xv[FIN];
    if (half==0) {
        const float* xr = x + ((size_t)b*TT)*FIN;
        #pragma unroll
        for (int f=0;f<FIN;f++) xv[f]=__ldg(xr+f);
    }

    for (int t=0;t<TT;t++) {
        size_t row = (size_t)b*TT + t;
        if (half==0) {
            float hv = bin;
            #pragma unroll
            for (int f=0;f<FIN;f++) hv = fmaf(xv[f], s_wi[f*64+j], hv);
            g_h[row*64+j] = hv;
            s_z[j] = hv;
            if (j<7) {
                float xp=0.f;
                #pragma unroll
                for (int kx=0;kx<7;kx++) xp = fmaf(s_A[j*7+kx], s_x[kx], xp);
                s_z[64+j] = xp;
            }
            if (j<49) s_K[t&1][j] = g_K[t*49+j];
            if (t+1 < TT) {
                const float* xr = x + (row+1)*FIN;
                #pragma unroll
                for (int f=0;f<FIN;f++) xv[f]=__ldg(xr+f);
            }
        }
        __syncthreads();
        u64 pA = 0ULL, pB = 0ULL;
        const ulonglong2* zp = (const ulonglong2*)&s_z[half*68];
        #pragma unroll
        for (int k2 = 0; k2 < 17; k2++) {
            ulonglong2 zv = zp[k2];
            pA = f2fma(zv.x, w2[2*k2],   pA);
            pB = f2fma(zv.y, w2[2*k2+1], pB);
        }
        float u0,u1,u2,u3;
        unpk(pA, u0, u1); unpk(pB, u2, u3);
        s_part[half][j] = (u0+u1)+(u2+u3);
        __syncthreads();
        if (half==0) {
            float a = s_part[0][j] + s_part[1][j] + bex;
            float hn = tanhf(a);
            s_z[71+j] = hn;
            asm volatile("bar.sync 1, 64;" ::: "memory");
            if (j<7) {
                float m0 = bme, m1 = 0.f, m2 = 0.f, m3 = 0.f;
                #pragma unroll
                for (int k=0;k<64;k+=4) {
                    m0 = fmaf(s_z[71+k+0], s_wm[(k+0)*7+j], m0);
                    m1 = fmaf(s_z[71+k+1], s_wm[(k+1)*7+j], m1);
                    m2 = fmaf(s_z[71+k+2], s_wm[(k+2)*7+j], m2);
                    m3 = fmaf(s_z[71+k+3], s_wm[(k+3)*7+j], m3);
                }
                float inn = ((m0+m1)+(m2+m3)) - s_z[64+j];
                s_innov[j] = inn;
                dout[OFF_INNOV + row*7 + j] = inn;
                acc2 = fmaf(inn, inn, acc2);
            }
            __syncwarp();
            if (j<7) {
                float xn = s_z[64+j];
                #pragma unroll
                for (int kx=0;kx<7;kx++) xn = fmaf(s_K[t&1][j*7+kx], s_innov[kx], xn);
                s_x[j] = xn;
                dout[OFF_STATE + row*7 + j] = xn;
            }
            __syncwarp();
        }
    }
    if (half==0) {
        acc2 += __shfl_down_sync(0xffffffffu, acc2, 4);
        acc2 += __shfl_down_sync(0xffffffffu, acc2, 2);
        acc2 += __shfl_down_sync(0xffffffffu, acc2, 1);
        if (j==0) g_chaos[b] = acc2;
        if (j<7) dout[OFF_XFIN + b*7 + j] = s_x[j];
    }
}

// ---------------- K2: gate + uncertainty ----------------
__global__ void k2_gate(const float* __restrict__ hurst,
                        const float* __restrict__ Wp, const float* __restrict__ bp,
                        float* __restrict__ dout)
{
    int idx = blockIdx.x*256 + threadIdx.x;
    if (idx >= BB*NH) return;
    int b = idx >> 2, h = idx & 3;
    float c = fminf(g_chaos[b] * (1.f/896.f), 10.f) * 0.1f;
    float z = c*Wp[h] + hurst[b]*Wp[4+h] + bp[h];
    g_gate[idx] = 1.f / (1.f + __expf(-z));
    if (h==0) dout[OFF_UNC + b] = g_trace;
}

__device__ __forceinline__ void gemm2col(
    const float* __restrict__ Wg, const float* __restrict__ bg,
    float* __restrict__ outg, const float* s_a, int cp, int rg, int r0)
{
    u64 w0[32], w1[32];
    #pragma unroll
    for (int k2 = 0; k2 < 32; k2++) {
        float2 ra = *(const float2*)&Wg[(2*k2)*64 + cp];
        float2 rb = *(const float2*)&Wg[(2*k2+1)*64 + cp];
        w0[k2] = pk(ra.x, rb.x);
        w1[k2] = pk(ra.y, rb.y);
    }
    float b0 = bg[cp], b1 = bg[cp+1];
    for (int rr = 0; rr < 16; rr++) {
        int lr = rg*16 + rr;
        const ulonglong2* ap = (const ulonglong2*)(s_a + lr*64);
        u64 x01 = 0ULL, x23 = 0ULL, y01 = 0ULL, y23 = 0ULL;
        #pragma unroll
        for (int k4 = 0; k4 < 16; k4++) {
            ulonglong2 av = ap[k4];
            x01 = f2fma(av.x, w0[2*k4],   x01);
            x23 = f2fma(av.y, w0[2*k4+1], x23);
            y01 = f2fma(av.x, w1[2*k4],   y01);
            y23 = f2fma(av.y, w1[2*k4+1], y23);
        }
        float xa,xb,xc,xd, ya,yb,yc,yd;
        unpk(x01,xa,xb); unpk(x23,xc,xd);
        unpk(y01,ya,yb); unpk(y23,yc,yd);
        *(float2*)&outg[(size_t)(r0+lr)*64 + cp] =
            make_float2(b0 + (xa+xb)+(xc+xd), b1 + (ya+yb)+(yc+yd));
    }
}

// ---------------- K3: fused a_in + QKV (proven) ----------------
__global__ __launch_bounds__(128) void k3_ain_qkv(
    const float* __restrict__ Wa, const float* __restrict__ ba,
    const float* __restrict__ Wq, const float* __restrict__ bq,
    const float* __restrict__ Wk, const float* __restrict__ bk,
    const float* __restrict__ Wv, const float* __restrict__ bv,
    const float* __restrict__ dout)
{
    __shared__ __align__(16) float s_in[64*72];
    __shared__ __align__(16) float s_a[64*64];
    int tid = threadIdx.x;
    int r0 = blockIdx.x * 64;
    for (int i = tid; i < 64*72; i += 128) {
        int lr = i / 72, c = i - lr*72;
        float v;
        if (c < 64)      v = g_h[(size_t)(r0+lr)*64 + c];
        else if (c < 71) v = dout[OFF_STATE + (size_t)(r0+lr)*7 + (c-64)];
        else             v = 0.f;
        s_in[i] = v;
    }
    __syncthreads();
    int cp = (tid & 31) * 2;
    int rg = tid >> 5;
    {
        u64 w0[36], w1[36];
        #pragma unroll
        for (int k2 = 0; k2 < 36; k2++) {
            int ka = 2*k2, kb = 2*k2+1;
            float2 ra = (ka < 71) ? *(const float2*)&Wa[ka*64 + cp] : make_float2(0.f,0.f);
            float2 rb = (kb < 71) ? *(const float2*)&Wa[kb*64 + cp] : make_float2(0.f,0.f);
            w0[k2] = pk(ra.x, rb.x);
            w1[k2] = pk(ra.y, rb.y);
        }
        float b0 = ba[cp], b1 = ba[cp+1];
        for (int rr = 0; rr < 16; rr++) {
            int lr = rg*16 + rr;
            const ulonglong2* ip = (const ulonglong2*)(s_in + lr*72);
            u64 x01=0ULL, x23=0ULL, y01=0ULL, y23=0ULL;
            #pragma unroll
            for (int k4 = 0; k4 < 18; k4++) {
                ulonglong2 iv = ip[k4];
                x01 = f2fma(iv.x, w0[2*k4],   x01);
                x23 = f2fma(iv.y, w0[2*k4+1], x23);
                y01 = f2fma(iv.x, w1[2*k4],   y01);
                y23 = f2fma(iv.y, w1[2*k4+1], y23);
            }
            float xa,xb,xc,xd, ya,yb,yc,yd;
            unpk(x01,xa,xb); unpk(x23,xc,xd);
            unpk(y01,ya,yb); unpk(y23,yc,yd);
            s_a[lr*64 + cp]   = b0 + (xa+xb)+(xc+xd);
            s_a[lr*64 + cp+1] = b1 + (ya+yb)+(yc+yd);
        }
    }
    __syncthreads();
    gemm2col(Wq, bq, g_q, s_a, cp, rg, r0);
    gemm2col(Wk, bk, g_k, s_a, cp, rg, r0);
    gemm2col(Wv, bv, g_v, s_a, cp, rg, r0);
}

// ---------------- K4: attention, chunked softmax, gate folded into Q (proven) ----------------
__global__ __launch_bounds__(64) void k4_attn()
{
    __shared__ __align__(16) float k_s[128*16];
    __shared__ __align__(16) float v_s[128*16];
    int bh = blockIdx.x;
    int b = bh >> 2, h = bh & 3;
    int tid = threadIdx.x;
    size_t base = ((size_t)b*TT)*64 + h*HD;

    for (int r = tid; r < 128; r += 64) {
        const float4* kg = (const float4*)&g_k[base + (size_t)r*64];
        float4* ks = (float4*)&k_s[r*16];
        ks[0]=kg[0]; ks[1]=kg[1]; ks[2]=kg[2]; ks[3]=kg[3];
        const float4* vg = (const float4*)&g_v[base + (size_t)r*64];
        float4* vs = (float4*)&v_s[r*16];
        vs[0]=vg[0]; vs[1]=vg[1]; vs[2]=vg[2]; vs[3]=vg[3];
    }
    int qA = tid*2, qB = tid*2 + 1;
    const ulonglong2* qap = (const ulonglong2*)&g_q[base + (size_t)qA*64];
    const ulonglong2* qbp = (const ulonglong2*)&g_q[base + (size_t)qB*64];
    ulonglong2 qa01 = qap[0], qa23 = qap[1], qa45 = qap[2], qa67 = qap[3];
    ulonglong2 qb01 = qbp[0], qb23 = qbp[1], qb45 = qbp[2], qb67 = qbp[3];
    float sc = g_gate[b*NH + h] * 0.25f;
    u64 sc2 = pk(sc, sc);
    qa01.x = f2mul(qa01.x, sc2); qa01.y = f2mul(qa01.y, sc2);
    qa23.x = f2mul(qa23.x, sc2); qa23.y = f2mul(qa23.y, sc2);
    qa45.x = f2mul(qa45.x, sc2); qa45.y = f2mul(qa45.y, sc2);
    qa67.x = f2mul(qa67.x, sc2); qa67.y = f2mul(qa67.y, sc2);
    qb01.x = f2mul(qb01.x, sc2); qb01.y = f2mul(qb01.y, sc2);
    qb23.x = f2mul(qb23.x, sc2); qb23.y = f2mul(qb23.y, sc2);
    qb45.x = f2mul(qb45.x, sc2); qb45.y = f2mul(qb45.y, sc2);
    qb67.x = f2mul(qb67.x, sc2); qb67.y = f2mul(qb67.y, sc2);
    __syncthreads();

    float mA = -1e30f, lA = 0.f, mB = -1e30f, lB = 0.f;
    u64 accA[8], accB[8];
    #pragma unroll
    for (int d = 0; d < 8; d++) { accA[d]=0ULL; accB[d]=0ULL; }
    float sA8[8], sB8[8];

    for (int c = 0; c < 16; c++) {
        int kk0 = c*8;
        float cmA = -1e30f, cmB = -1e30f;
        #pragma unroll
        for (int i = 0; i < 8; i++) {
            const ulonglong2* kr = (const ulonglong2*)&k_s[(kk0+i)*16];
            ulonglong2 k01 = kr[0], k23 = kr[1], k45 = kr[2], k67 = kr[3];
            u64 dA = f2mul(qa01.x, k01.x);
            dA = f2fma(qa01.y, k01.y, dA);
            dA = f2fma(qa23.x, k23.x, dA);
            dA = f2fma(qa23.y, k23.y, dA);
            dA = f2fma(qa45.x, k45.x, dA);
            dA = f2fma(qa45.y, k45.y, dA);
            dA = f2fma(qa67.x, k67.x, dA);
            dA = f2fma(qa67.y, k67.y, dA);
            u64 dB = f2mul(qb01.x, k01.x);
            dB = f2fma(qb01.y, k01.y, dB);
            dB = f2fma(qb23.x, k23.x, dB);
            dB = f2fma(qb23.y, k23.y, dB);
            dB = f2fma(qb45.x, k45.x, dB);
            dB = f2fma(qb45.y, k45.y, dB);
            dB = f2fma(qb67.x, k67.x, dB);
            dB = f2fma(qb67.y, k67.y, dB);
            float a0,a1,b0,b1;
            unpk(dA, a0, a1); unpk(dB, b0, b1);
            float sA = a0+a1, sB = b0+b1;
            sA8[i] = sA; sB8[i] = sB;
            cmA = fmaxf(cmA, sA); cmB = fmaxf(cmB, sB);
        }
        float mnA = fmaxf(mA, cmA), mnB = fmaxf(mB, cmB);
        float rA = __expf(mA - mnA), rB = __expf(mB - mnB);
        mA = mnA; mB = mnB;
        lA *= rA; lB *= rB;
        u64 rA2 = pk(rA, rA), rB2 = pk(rB, rB);
        #pragma unroll
        for (int d = 0; d < 8; d++) {
            accA[d] = f2mul(accA[d], rA2);
            accB[d] = f2mul(accB[d], rB2);
        }
        #pragma unroll
        for (int i = 0; i < 8; i++) {
            float pA = __expf(sA8[i] - mA);
            float pB = __expf(sB8[i] - mB);
            lA += pA; lB += pB;
            u64 pA2 = pk(pA, pA), pB2 = pk(pB, pB);
            const ulonglong2* vr = (const ulonglong2*)&v_s[(kk0+i)*16];
            ulonglong2 v01 = vr[0], v23 = vr[1], v45 = vr[2], v67 = vr[3];
            accA[0] = f2fma(pA2, v01.x, accA[0]);
            accA[1] = f2fma(pA2, v01.y, accA[1]);
            accA[2] = f2fma(pA2, v23.x, accA[2]);
            accA[3] = f2fma(pA2, v23.y, accA[3]);
            accA[4] = f2fma(pA2, v45.x, accA[4]);
            accA[5] = f2fma(pA2, v45.y, accA[5]);
            accA[6] = f2fma(pA2, v67.x, accA[6]);
            accA[7] = f2fma(pA2, v67.y, accA[7]);
            accB[0] = f2fma(pB2, v01.x, accB[0]);
            accB[1] = f2fma(pB2, v01.y, accB[1]);
            accB[2] = f2fma(pB2, v23.x, accB[2]);
            accB[3] = f2fma(pB2, v23.y, accB[3]);
            accB[4] = f2fma(pB2, v45.x, accB[4]);
            accB[5] = f2fma(pB2, v45.y, accB[5]);
            accB[6] = f2fma(pB2, v67.x, accB[6]);
            accB[7] = f2fma(pB2, v67.y, accB[7]);
        }
    }
    float invA = 1.f / lA, invB = 1.f / lB;
    float oA[16], oB[16];
    #pragma unroll
    for (int d = 0; d < 8; d++) {
        unpk(accA[d], oA[2*d], oA[2*d+1]);
        unpk(accB[d], oB[2*d], oB[2*d+1]);
    }
    float4* oa = (float4*)&g_ctx[base + (size_t)qA*64];
    float4* ob = (float4*)&g_ctx[base + (size_t)qB*64];
    #pragma unroll
    for (int d = 0; d < 4; d++) {
        oa[d] = make_float4(oA[4*d]*invA, oA[4*d+1]*invA, oA[4*d+2]*invA, oA[4*d+3]*invA);
        ob[d] = make_float4(oB[4*d]*invB, oB[4*d+1]*invB, oB[4*d+2]*invB, oB[4*d+3]*invB);
    }
}

// ---------------- K5: attn_out + fused pheno + fused partial pooling (proven) ----------------
__global__ __launch_bounds__(128) void k5_wo(
    const float* __restrict__ Wo, const float* __restrict__ bo,
    const float* __restrict__ Wp, const float* __restrict__ bp,
    float* __restrict__ dout)
{
    __shared__ __align__(16) float s_c[64*64];
    __shared__ __align__(16) float s_o[64*72];
    __shared__ float s_wp[448];
    __shared__ float s_ps[4][64];
    int tid = threadIdx.x;
    int r0 = blockIdx.x * 64;
    for (int i = tid; i < 4096; i += 128) s_c[i] = g_ctx[(size_t)r0*64 + i];
    for (int i = tid; i < 448; i += 128) s_wp[i] = Wp[i];
    __syncthreads();
    int cp = (tid & 31) * 2;
    int rg = tid >> 5;
    {
        u64 w0[32], w1[32];
        #pragma unroll
        for (int k2 = 0; k2 < 32; k2++) {
            float2 ra = *(const float2*)&Wo[(2*k2)*64 + cp];
            float2 rb = *(const float2*)&Wo[(2*k2+1)*64 + cp];
            w0[k2] = pk(ra.x, rb.x);
            w1[k2] = pk(ra.y, rb.y);
        }
        float b0 = bo[cp], b1 = bo[cp+1];
        float ps0 = 0.f, ps1 = 0.f;
        for (int rr = 0; rr < 16; rr++) {
            int lr = rg*16 + rr;
            const ulonglong2* ap = (const ulonglong2*)(s_c + lr*64);
            u64 x01 = 0ULL, x23 = 0ULL, y01 = 0ULL, y23 = 0ULL;
            #pragma unroll
            for (int k4 = 0; k4 < 16; k4++) {
                ulonglong2 av = ap[k4];
                x01 = f2fma(av.x, w0[2*k4],   x01);
                x23 = f2fma(av.y, w0[2*k4+1], x23);
                y01 = f2fma(av.x, w1[2*k4],   y01);
                y23 = f2fma(av.y, w1[2*k4+1], y23);
            }
            float xa,xb,xc,xd, ya,yb,yc,yd;
            unpk(x01,xa,xb); unpk(x23,xc,xd);
            unpk(y01,ya,yb); unpk(y23,yc,yd);
            float o0 = b0 + (xa+xb)+(xc+xd);
            float o1 = b1 + (ya+yb)+(yc+yd);
            ps0 += o0; ps1 += o1;
            *(float2*)&g_ao[(size_t)(r0+lr)*64 + cp] = make_float2(o0, o1);
            *(float2*)&s_o[lr*72 + cp] = make_float2(o0, o1);
        }
        s_ps[rg][cp] = ps0;
        s_ps[rg][cp+1] = ps1;
    }
    __syncthreads();
    if (tid < 64) {
        g_pool[(size_t)blockIdx.x*64 + tid] =
            s_ps[0][tid] + s_ps[1][tid] + s_ps[2][tid] + s_ps[3][tid];
    }
    for (int o = tid; o < 448; o += 128) {
        int lr = o / 7, n = o - lr*7;
        float a0 = bp[n], a1 = 0.f, a2 = 0.f, a3 = 0.f;
        const float4* tp = (const float4*)(s_o + lr*72);
        #pragma unroll
        for (int k4 = 0; k4 < 16; k4++) {
            float4 tv = tp[k4];
            a0 = fmaf(tv.x, s_wp[(4*k4+0)*7 + n], a0);
            a1 = fmaf(tv.y, s_wp[(4*k4+1)*7 + n], a1);
            a2 = fmaf(tv.z, s_wp[(4*k4+2)*7 + n], a2);
            a3 = fmaf(tv.w, s_wp[(4*k4+3)*7 + n], a3);
        }
        dout[OFF_PHENO + (size_t)(r0+lr)*7 + n] = (a0+a1)+(a2+a3);
    }
}

// ---------------- K6: LN + crop from pooled partials (proven) ----------------
__global__ __launch_bounds__(64) void k6_pool(
    const float* __restrict__ lng, const float* __restrict__ lnb,
    const float* __restrict__ Wc, const float* __restrict__ bc,
    float* __restrict__ dout)
{
    __shared__ float s_y[64];
    __shared__ float red[2];
    int b = blockIdx.x, tid = threadIdx.x;
    float pool = (g_pool[(size_t)(2*b)*64 + tid] + g_pool[(size_t)(2*b+1)*64 + tid]) * (1.f/128.f);
    float v = pool;
    #pragma unroll
    for (int off = 16; off >= 1; off >>= 1) v += __shfl_down_sync(0xffffffffu, v, off);
    if ((tid & 31) == 0) red[tid >> 5] = v;
    __syncthreads();
    float mean = (red[0] + red[1]) * (1.f/64.f);
    __syncthreads();
    float d = pool - mean;
    v = d * d;
    #pragma unroll
    for (int off = 16; off >= 1; off >>= 1) v += __shfl_down_sync(0xffffffffu, v, off);
    if ((tid & 31) == 0) red[tid >> 5] = v;
    __syncthreads();
    float var = (red[0] + red[1]) * (1.f/64.f);
    float y = d * rsqrtf(var + 1e-5f) * lng[tid] + lnb[tid];
    s_y[tid] = y;
    __syncthreads();
    if (tid < 3) {
        float acc = bc[tid];
        #pragma unroll 8
        for (int jx = 0; jx < 64; jx++) acc += s_y[jx] * Wc[jx*3 + tid];
        dout[OFF_CROP + b*3 + tid] = acc;
    }
}

extern "C" void kernel_launch(void* const* d_in, const int* in_sizes, int n_in,
                              void* d_out, int out_size)
{
    const float* x      = (const float*)d_in[0];
    const float* hurst  = (const float*)d_in[2];
    const float* W_in   = (const float*)d_in[3];
    const float* b_in   = (const float*)d_in[4];
    const float* W_exec = (const float*)d_in[5];
    const float* b_exec = (const float*)d_in[6];
    const float* W_meas = (const float*)d_in[7];
    const float* b_meas = (const float*)d_in[8];
    const float* A      = (const float*)d_in[9];
    const float* W_attn = (const float*)d_in[10];
    const float* b_attn = (const float*)d_in[11];
    const float* Wq     = (const float*)d_in[12];
    const float* bq     = (const float*)d_in[13];
    const float* Wk     = (const float*)d_in[14];
    const float* bk     = (const float*)d_in[15];
    const float* Wv     = (const float*)d_in[16];
    const float* bv     = (const float*)d_in[17];
    const float* Wo     = (const float*)d_in[18];
    const float* bo     = (const float*)d_in[19];
    const float* W_phys = (const float*)d_in[20];
    const float* b_phys = (const float*)d_in[21];
    const float* ln_g   = (const float*)d_in[22];
    const float* ln_b   = (const float*)d_in[23];
    const float* W_crop = (const float*)d_in[24];
    const float* b_crop = (const float*)d_in[25];
    const float* W_phen = (const float*)d_in[26];
    const float* b_phen = (const float*)d_in[27];
    float* out = (float*)d_out;

    k0_riccati<<<1, 64>>>(A, 0,  43, 1, 0);
    k0_riccati<<<1, 64>>>(A, 43, 86, 0, 0);
    k0_riccati<<<1, 64>>>(A, 86, 128, 0, 1);
    k1_scan<<<BB, 128>>>(x, W_in, b_in, W_exec, b_exec, W_meas, b_meas, A, out);
    k2_gate<<<(BB*NH + 255)/256, 256>>>(hurst, W_phys, b_phys, out);
    k3_ain_qkv<<<MROWS/64, 128>>>(W_attn, b_attn, Wq, bq, Wk, bk, Wv, bv, out);
    k4_attn<<<BB*NH, 64>>>();
    k5_wo<<<MROWS/64, 128>>>(Wo, bo, W_phen, b_phen, out);
    k6_pool<<<BB, 64>>>(ln_g, ln_b, W_crop, b_crop, out);
}